// round 11
// baseline (speedup 1.0000x reference)
#include <cuda_runtime.h>
#include <math.h>

#define NBOX 8192
#define LCLS 8
#define CAP   1536         // total per-label capacity
#define NBUCK 8
#define BCAP  192          // per-bucket capacity (mean 128, +6 sigma)
#define NT    256
#define NW    (NT / 32)
#define MAXK  6            // BCAP / 32
#define FULLMASK 0xffffffffu

// Scratch (no allocations allowed): per-label keep lists + counts.
__device__ int d_keep[LCLS * CAP];
__device__ int d_kc[LCLS];

// ---------------------------------------------------------------------------
// float-float exp(x) for x in [-2, 0], FFMA-only, branchless (validated
// bit-exact vs jax f32 exp in R3/R6/R7/R9: rel_err 0.0). exp_ff(-0.0) == 1.0f
// exactly, so unconditional application to non-overlapping boxes reproduces
// the reference's vectorized cs*decay bit-for-bit.
// ---------------------------------------------------------------------------
__device__ __forceinline__ float exp_ff(float x, const float2* __restrict__ tab,
                                        float L2c, float L3c)
{
    const float I   = 738.66585811433f;   // 512/ln2
    const float L1c = 0x1.62ep-10f;       // 13-bit head of ln2/512 (n*L1 exact)

    float nf = rintf(x * I);
    int   n  = (int)nf;
    float a  = fmaf(-nf, L1c, x);         // exact
    float t  = nf * L2c;
    float b   = -t;
    float rh  = a + b;
    float bb  = rh - a;
    float err = (a - (rh - bb)) + (b - bb);
    float dt  = fmaf(nf, L2c, -t);        // exact rounding residual of t
    float rl  = err - dt - nf * L3c;
    float q = fmaf(rh, 0.041666668f, 0.16666667f);
    q       = fmaf(rh, q, 0.5f);
    float s = (rh * rh) * q;
    float uh  = 1.0f + rh;
    float ul  = rh - (uh - 1.0f);
    float low = (ul + rl) + s;
    float mh  = uh + low;
    float ml  = low - (mh - uh);
    int e = n >> 9;
    int k = n - (e << 9);
    float2 T = tab[k];
    float ph = T.x * mh;
    float pl = fmaf(T.x, mh, -ph);        // exact
    pl = fmaf(T.x, ml, pl);
    pl = fmaf(T.y, mh, pl);
    float se = __int_as_float((127 + e) << 23);   // 2^e, e in [-3,0]
    return fmaf(ph, se, pl * se);
}

__global__ __launch_bounds__(NT, 1)
void softnms_kernel(const float4* __restrict__ boxes,
                    const float* __restrict__ scores,
                    const int* __restrict__ labels)
{
    const int l    = blockIdx.x;
    const int t    = threadIdx.x;
    const int warp = t >> 5;
    const int lane = t & 31;

    __shared__ float4   sBox[CAP];        // by storage position (bucketed)
    __shared__ float    sSc[CAP];
    __shared__ int      sPO[CAP];         // storage -> original compacted position
    __shared__ int      sOrd[CAP];        // original position -> global box index
    __shared__ float2   sTab[512];
    __shared__ float    sL2c, sL3c;
    __shared__ int      sWCnt[NW];
    __shared__ int      bCnt[NBUCK];
    __shared__ uint4    bPost[2][NW];     // {key, storagePos, rankPart, pOrig}
    __shared__ int      sBase;

    // ---------------- one-time prologue: exp table + constants ----------------
    for (int q = t; q < 512; q += NT) {
        double v = exp2((double)q * (1.0 / 512.0));
        float hi = (float)v;
        sTab[q] = make_float2(hi, (float)(v - (double)hi));
    }
    if (t == 0) {
        double Ld = 0.69314718055994530941723212145818 / 512.0;
        const float L1c = 0x1.62ep-10f;
        float l2 = (float)(Ld - (double)L1c);
        sL2c = l2;
        sL3c = (float)(Ld - (double)L1c - (double)l2);
        sBase = 0;
    }
    if (t < NBUCK) bCnt[t] = 0;
    __syncthreads();

    // ------- stable per-label compaction (pOrig order) + x-bucket scatter -----
    for (int start = 0; start < NBOX; start += NT) {
        const int j = start + t;
        const bool flag = (labels[j] == l);
        const unsigned ball = __ballot_sync(FULLMASK, flag);
        const int wpre = __popc(ball & ((1u << lane) - 1u));
        if (lane == 0) sWCnt[warp] = __popc(ball);
        __syncthreads();
        int pre = 0, tot = 0;
#pragma unroll
        for (int w = 0; w < NW; w++) {
            const int c = sWCnt[w];
            if (w < warp) pre += c;
            tot += c;
        }
        if (flag) {
            const int p = sBase + pre + wpre;   // original compacted position
            if (p < CAP) {
                sOrd[p] = j;
                const float4 bb = boxes[j];
                int b = (int)(bb.x * 0.008f);   // x1 in [0,1000) -> 8 strips of 125
                b = max(0, min(NBUCK - 1, b));
                const int idx = atomicAdd(&bCnt[b], 1);
                if (idx < BCAP) {
                    const int st = b * BCAP + idx;
                    sBox[st] = bb;
                    sSc[st]  = scores[j];
                    sPO[st]  = p;
                }
            }
        }
        __syncthreads();
        if (t == 0) sBase += tot;
        __syncthreads();
    }

    const int cnt = min(bCnt[warp], BCAP);     // my bucket's element count
    const int Kw  = (cnt + 31) >> 5;           // my slots
    const float L2c = sL2c, L3c = sL3c;

    // Per-lane register-resident working set (strided within bucket)
    float ws[MAXK], ax[MAXK], ay[MAXK], bx[MAXK], by[MAXK], area[MAXK];
    int   po[MAXK];
#pragma unroll
    for (int k = 0; k < MAXK; k++) {
        const int e  = (k << 5) + lane;
        const bool v = (k < Kw) && (e < cnt);
        const int st = warp * BCAP + e;
        ws[k] = v ? sSc[st] : -1.0f;
        po[k] = v ? sPO[st] : 0x7fffffff;
        const float4 bb = v ? sBox[st] : make_float4(0.f, 0.f, 0.f, 0.f);
        ax[k] = bb.x; ay[k] = bb.y; bx[k] = bb.z; by[k] = bb.w;
        area[k] = (bb.z - bb.x) * (bb.w - bb.y);
    }

    // ---------------- initial scan -> cached post {key, stor, pOrig} ----------
    unsigned cKey, cSt, cPo;
    {
        unsigned lkey = 0u, lst = 0u;
        int lpo = 0x7fffffff;
#pragma unroll
        for (int k = 0; k < MAXK; k++) {
            if (k >= Kw) break;
            const float sc = ws[k];
            if (sc >= 0.0f) {
                const unsigned b = __float_as_uint(sc);
                if (b > lkey || (b == lkey && po[k] < lpo)) {
                    lkey = b; lpo = po[k];
                    lst = (unsigned)(warp * BCAP + (k << 5) + lane);
                }
            }
        }
        const unsigned wkey = __reduce_max_sync(FULLMASK, lkey);
        const int qpo  = (lkey == wkey) ? lpo : 0x7fffffff;
        const int wpo  = __reduce_min_sync(FULLMASK, qpo);
        const unsigned ball = __ballot_sync(FULLMASK, (lkey == wkey) && (lpo == wpo));
        const int wl = __ffs(ball) - 1;
        const unsigned wst = __shfl_sync(FULLMASK, lst, wl);
        cKey = wkey; cSt = wst; cPo = (unsigned)wpo;
        if (lane == 0) bPost[0][warp] = make_uint4(cKey, cSt, 0u, cPo);
    }
    __syncthreads();

    // ---------------- sequential Soft-NMS loop -------------------------------
    const float wlo  = 125.0f * warp - 0.01f;  // left margin: bucket-index float
                                               // rounding can leak ~0.004px
    const float whiM = 125.0f * warp + 125.0f + 131.0f;  // strip + max width + slack
    int kc = 0, cur = 0;
    for (;;) {
        // combine 8 warp posts; tie -> min pOrig (exact jnp.argmax)
        unsigned bk = 0u, bst = 0u;
        int bpo = 0x7fffffff, rsum = 0;
#pragma unroll
        for (int w = 0; w < NW; w++) {
            const uint4 v = bPost[cur][w];
            rsum += (int)v.z;
            if (v.x > bk || (v.x == bk && (int)v.w < bpo)) {
                bk = v.x; bst = v.y; bpo = (int)v.w;
            }
        }
        // deferred keep-write for the PREVIOUS selection (off critical path)
        if (kc > 0 && t == 0) d_keep[l * CAP + (kc - 1)] = sOrd[rsum];
        if (bk == 0u) break;
        kc++;
        const int pSel = bpo;
        const float4 sb = sBox[bst];           // broadcast LDS

        // warp-level spatial skip; FORCED full sweep on the first selection so
        // latent sub-threshold boxes die everywhere (reference applies
        // cs>=SCORE_THR to all alive boxes each iteration; after a full pass 1
        // every alive untouched box provably stays >= thr).
        const bool activeW = (kc == 1) || ((wlo < sb.z) && (whiM > sb.x));
        int rloc = 0;
        if (activeW) {
            const float aS = (sb.z - sb.x) * (sb.w - sb.y);
            unsigned nkey = 0u, nst = 0u;
            int npo = 0x7fffffff;
#pragma unroll
            for (int k = 0; k < MAXK; k++) {
                if (k >= Kw) break;
                const float sc = ws[k];
                const int pk = po[k];
                rloc += ((sc >= 0.0f) & (pk < pSel)) ? 1 : 0;  // rank, pre-decay set
                // fully branchless decay (dec==1.0 exactly for non-overlap)
                const float lx = fmaxf(sb.x, ax[k]);
                const float ly = fmaxf(sb.y, ay[k]);
                const float rx = fminf(sb.z, bx[k]);
                const float ry = fminf(sb.w, by[k]);
                const float inter = fmaxf(rx - lx, 0.0f) * fmaxf(ry - ly, 0.0f);
                const float iou = inter / (aS + area[k] - inter + 1e-8f);
                const float arg = -(iou * iou) * 2.0f;
                const float dec = exp_ff(arg, sTab, L2c, L3c);
                const float nv = sc * dec;     // dead slots stay negative
                const bool keep = (nv >= 0.001f) & (pk != pSel);
                ws[k] = keep ? nv : -1.0f;
                const unsigned b = keep ? __float_as_uint(nv) : 0u;
                if (b > nkey || (b == nkey && pk < npo)) {
                    nkey = b; npo = pk;
                    nst = (unsigned)(warp * BCAP + (k << 5) + lane);
                }
            }
            const unsigned wkey = __reduce_max_sync(FULLMASK, nkey);
            const int qpo = (nkey == wkey) ? npo : 0x7fffffff;
            const int wpo = __reduce_min_sync(FULLMASK, qpo);
            const unsigned ball = __ballot_sync(FULLMASK, (nkey == wkey) && (npo == wpo));
            const int wl = __ffs(ball) - 1;
            const unsigned wst = __shfl_sync(FULLMASK, nst, wl);
            cKey = wkey; cSt = wst; cPo = (unsigned)wpo;
        } else {
            // untouched warp: scores & alive set unchanged -> cached post valid;
            // only the rank part depends on this iteration's pSel
#pragma unroll
            for (int k = 0; k < MAXK; k++) {
                if (k >= Kw) break;
                rloc += ((ws[k] >= 0.0f) & (po[k] < pSel)) ? 1 : 0;
            }
        }
        const int wrank = __reduce_add_sync(FULLMASK, rloc);
        if (lane == 0) bPost[cur ^ 1][warp] = make_uint4(cKey, cSt, (unsigned)wrank, cPo);
        __syncthreads();
        cur ^= 1;
    }

    if (t == 0) d_kc[l] = kc;
}

// ---------------- gather + pack outputs ----------------
// Layout (float32): boxes[N*4] | scores[N] | labels[N] | count[1]
__global__ void gather_kernel(const float4* __restrict__ boxes,
                              const float* __restrict__ scores,
                              const int* __restrict__ labels,
                              float* __restrict__ out)
{
    const int j = blockIdx.x * blockDim.x + threadIdx.x;

    int off[LCLS + 1];
    off[0] = 0;
#pragma unroll
    for (int l = 0; l < LCLS; l++) off[l + 1] = off[l] + d_kc[l];
    const int total = off[LCLS];

    if (j == 0) out[NBOX * 6] = (float)total;
    if (j >= NBOX) return;

    float4 b = make_float4(0.f, 0.f, 0.f, 0.f);
    float s = 0.f, lab = 0.f;
    if (j < total) {
        int l = 0;
#pragma unroll
        for (int q = 1; q < LCLS; q++) if (j >= off[q]) l = q;
        const int g = d_keep[l * CAP + (j - off[l])];
        b = boxes[g];
        s = scores[g];
        lab = (float)labels[g];
    }
    reinterpret_cast<float4*>(out)[j] = b;
    out[NBOX * 4 + j] = s;
    out[NBOX * 5 + j] = lab;
}

extern "C" void kernel_launch(void* const* d_in, const int* in_sizes, int n_in,
                              void* d_out, int out_size)
{
    const float4* boxes  = (const float4*)d_in[0];
    const float*  scores = (const float*)d_in[1];
    const int*    labels = (const int*)d_in[2];
    float* out = (float*)d_out;

    softnms_kernel<<<LCLS, NT>>>(boxes, scores, labels);
    gather_kernel<<<NBOX / NT, NT>>>(boxes, scores, labels, out);
}

// round 12
// speedup vs baseline: 2.9203x; 2.9203x over previous
#include <cuda_runtime.h>
#include <math.h>

#define NBOX 8192
#define LCLS 8
#define CAP  1536          // max boxes per label
#define NT   256
#define NW   (NT / 32)
#define MAXK 6
#define FULLMASK 0xffffffffu

// Scratch (no allocations allowed): per-label keep lists + counts.
__device__ int d_keep[LCLS * CAP];
__device__ int d_kc[LCLS];

// ---------------------------------------------------------------------------
// float-float exp(x) for x in [-2, 0], FFMA-only hot path (validated bit-exact
// vs jax f32 exp in R3/R6/R7/R9/R11: rel_err 0.0).
// ---------------------------------------------------------------------------
__device__ __forceinline__ float exp_ff(float x, const float2* __restrict__ tab,
                                        float L2c, float L3c)
{
    const float I   = 738.66585811433f;   // 512/ln2
    const float L1c = 0x1.62ep-10f;       // 13-bit head of ln2/512 (n*L1 exact)

    float nf = rintf(x * I);
    int   n  = (int)nf;
    float a  = fmaf(-nf, L1c, x);         // exact
    float t  = nf * L2c;
    float b   = -t;
    float rh  = a + b;
    float bb  = rh - a;
    float err = (a - (rh - bb)) + (b - bb);
    float dt  = fmaf(nf, L2c, -t);        // exact rounding residual of t
    float rl  = err - dt - nf * L3c;
    float q = fmaf(rh, 0.041666668f, 0.16666667f);
    q       = fmaf(rh, q, 0.5f);
    float s = (rh * rh) * q;
    float uh  = 1.0f + rh;
    float ul  = rh - (uh - 1.0f);
    float low = (ul + rl) + s;
    float mh  = uh + low;
    float ml  = low - (mh - uh);
    int e = n >> 9;
    int k = n - (e << 9);
    float2 T = tab[k];
    float ph = T.x * mh;
    float pl = fmaf(T.x, mh, -ph);        // exact
    pl = fmaf(T.x, ml, pl);
    pl = fmaf(T.y, mh, pl);
    float se = __int_as_float((127 + e) << 23);   // 2^e, e in [-3,0]
    return fmaf(ph, se, pl * se);
}

__global__ __launch_bounds__(NT, 1)
void softnms_kernel(const float4* __restrict__ boxes,
                    const float* __restrict__ scores,
                    const int* __restrict__ labels)
{
    const int l    = blockIdx.x;
    const int t    = threadIdx.x;
    const int warp = t >> 5;
    const int lane = t & 31;

    __shared__ float4   sBox[CAP];        // by CURRENT storage position
    __shared__ float    sSc[CAP];         // init: scores; later: repack staging
    __shared__ int      sOrd[CAP];        // ORIGINAL order -> global box index (never repacked)
    __shared__ float2   sTab[512];
    __shared__ float    sL2c, sL3c;
    __shared__ int      sWCnt[NW];
    __shared__ uint4    bPost[2][NW];     // {key, pos, rankPart, alivePart}
    __shared__ int      sBase;
    __shared__ int      sSelNew;          // selected's new position after repack

    // ---------------- one-time prologue: exp table + constants ----------------
    for (int q = t; q < 512; q += NT) {
        double v = exp2((double)q * (1.0 / 512.0));
        float hi = (float)v;
        sTab[q] = make_float2(hi, (float)(v - (double)hi));
    }
    if (t == 0) {
        double Ld = 0.69314718055994530941723212145818 / 512.0;
        const float L1c = 0x1.62ep-10f;
        float l2 = (float)(Ld - (double)L1c);
        sL2c = l2;
        sL3c = (float)(Ld - (double)L1c - (double)l2);
        sBase = 0;
    }
    __syncthreads();

    // ---------------- stable per-label compaction ----------------
    for (int start = 0; start < NBOX; start += NT) {
        const int j = start + t;
        const bool flag = (labels[j] == l);
        const unsigned ball = __ballot_sync(FULLMASK, flag);
        const int wpre = __popc(ball & ((1u << lane) - 1u));
        if (lane == 0) sWCnt[warp] = __popc(ball);
        __syncthreads();
        int pre = 0, tot = 0;
#pragma unroll
        for (int w = 0; w < NW; w++) {
            const int c = sWCnt[w];
            if (w < warp) pre += c;
            tot += c;
        }
        if (flag) {
            const int p = sBase + pre + wpre;
            if (p < CAP) {
                sOrd[p] = j;
                sSc[p]  = scores[j];
                sBox[p] = boxes[j];
            }
        }
        __syncthreads();
        if (t == 0) sBase += tot;
        __syncthreads();
    }

    const int m = min(sBase, CAP);
    int Kcur = (m + NT - 1) >> 8;          // ceil(m/256), <= MAXK
    const float L2c = sL2c, L3c = sL3c;

    // Per-thread register-resident working set (contiguous segment of Kcur)
    float ws[MAXK], ax[MAXK], ay[MAXK], bx[MAXK], by[MAXK], area[MAXK];
#pragma unroll
    for (int k = 0; k < MAXK; k++) {
        const int p = t * Kcur + k;
        const bool v = (k < Kcur) && (p < m);
        ws[k] = v ? sSc[p] : -1.0f;
        const float4 bb = v ? sBox[p] : make_float4(0.f, 0.f, 0.f, 0.f);
        ax[k] = bb.x; ay[k] = bb.y; bx[k] = bb.z; by[k] = bb.w;
        area[k] = (bb.z - bb.x) * (bb.w - bb.y);
    }

    // ---------------- initial scan -> post {key, pos, 0, aliveCnt} ------------
    {
        unsigned lkey = 0u, lpp = 0u;
        int acnt = 0;
#pragma unroll
        for (int k = 0; k < MAXK; k++) {
            if (k >= Kcur) break;
            if (ws[k] >= 0.0f) {
                acnt++;
                const unsigned b = __float_as_uint(ws[k]);
                if (b > lkey) { lkey = b; lpp = (unsigned)(t * Kcur + k); }
            }
        }
        const unsigned wmax = __reduce_max_sync(FULLMASK, lkey);
        const unsigned ball = __ballot_sync(FULLMASK, lkey == wmax);
        const int wl = __ffs(ball) - 1;
        const unsigned wpp = __shfl_sync(FULLMASK, lpp, wl);
        const int wal = __reduce_add_sync(FULLMASK, acnt);
        if (lane == 0) bPost[0][warp] = make_uint4(wmax, wpp, 0u, (unsigned)wal);
    }
    __syncthreads();

    // ---------------- sequential Soft-NMS loop -------------------------------
    int kc = 0, cur = 0;
    for (;;) {
        // combine the 8 warp posts (ascending warp order + strict '>' =>
        // exact jnp.argmax first-max, since positions ascend with warp/lane/k)
        unsigned bk = 0u, bpp = 0u;
        int rsum = 0, asum = 0;
#pragma unroll
        for (int w = 0; w < NW; w++) {
            const uint4 v = bPost[cur][w];
            if (v.x > bk) { bk = v.x; bpp = v.y; }
            rsum += (int)v.z;
            asum += (int)v.w;
        }
        // deferred keep-write for the PREVIOUS selection (off critical path);
        // rsum = alive-rank, indexed into the ORIGINAL-order list (ref bug)
        if (kc > 0 && t == 0) d_keep[l * CAP + (kc - 1)] = sOrd[rsum];
        if (bk == 0u) break;
        kc++;
        int pSel = (int)bpp;
        const float4 sb = sBox[bpp];       // read BEFORE any repack overwrites sBox

        // ---------- repack: stable in-place compaction of the alive set ------
        const int Knew = (asum + NT - 1) >> 8;    // asum >= 1 here
        if (Knew < Kcur) {
            // exclusive prefix of per-thread alive counts
            int myA = 0;
#pragma unroll
            for (int k = 0; k < MAXK; k++) {
                if (k >= Kcur) break;
                myA += (ws[k] >= 0.0f) ? 1 : 0;
            }
            int incl = myA;
#pragma unroll
            for (int off = 1; off < 32; off <<= 1) {
                const int nb = __shfl_up_sync(FULLMASK, incl, off);
                if (lane >= off) incl += nb;
            }
            if (lane == 31) sWCnt[warp] = incl;
            __syncthreads();
            int basep = 0;
#pragma unroll
            for (int w = 0; w < NW; w++) if (w < warp) basep += sWCnt[w];
            int np = basep + (incl - myA);        // my first alive's new position
            // stage alive (score, box) to new positions; record selected's new pos
#pragma unroll
            for (int k = 0; k < MAXK; k++) {
                if (k >= Kcur) break;
                if (ws[k] >= 0.0f) {
                    sSc[np]  = ws[k];
                    sBox[np] = make_float4(ax[k], ay[k], bx[k], by[k]);
                    if (t * Kcur + k == pSel) sSelNew = np;
                    np++;
                }
            }
            __syncthreads();
            // reload with Knew contiguous slots per thread
#pragma unroll
            for (int k = 0; k < MAXK; k++) {
                const int p = t * Knew + k;
                const bool v = (k < Knew) && (p < asum);
                ws[k] = v ? sSc[p] : -1.0f;
                const float4 bb = v ? sBox[p] : make_float4(0.f, 0.f, 0.f, 0.f);
                ax[k] = bb.x; ay[k] = bb.y; bx[k] = bb.z; by[k] = bb.w;
                area[k] = (bb.z - bb.x) * (bb.w - bb.y);
            }
            pSel = sSelNew;                       // after the bar: visible
            Kcur = Knew;
            __syncthreads();                      // reloads done before next staging
        }
        const int pBase = t * Kcur;

        // ---------- fused decay + next-argmax + rank + alive-count sweep -----
        unsigned nkey = 0u, npp = 0u;
        int rloc = 0, kloc = 0;
#pragma unroll
        for (int k = 0; k < MAXK; k++) {
            if (k >= Kcur) break;
            const float sc = ws[k];
            const bool alive = (sc >= 0.0f);
            const int p = pBase + k;
            rloc += (alive & (p < pSel)) ? 1 : 0;    // rank vs pre-decay alive set
            const float lx = fmaxf(sb.x, ax[k]);
            const float ly = fmaxf(sb.y, ay[k]);
            const float rx = fminf(sb.z, bx[k]);
            const float ry = fminf(sb.w, by[k]);
            const float inter = fmaxf(rx - lx, 0.0f) * fmaxf(ry - ly, 0.0f);
            const bool hot = alive & (inter > 0.0f) & (p != pSel);
            float nv = sc;
            if (hot) {                     // rare {div, exp} region
                const float aS  = (sb.z - sb.x) * (sb.w - sb.y);
                const float iou = inter / (aS + area[k] - inter + 1e-8f);
                const float arg = -(iou * iou) * 2.0f;
                nv = sc * exp_ff(arg, sTab, L2c, L3c);
            }
            // SCORE_THR re-applied to ALL alive boxes every iteration
            const bool keep = (nv >= 0.001f) & (p != pSel);
            ws[k] = keep ? nv : -1.0f;
            kloc += keep ? 1 : 0;
            const unsigned b = keep ? __float_as_uint(nv) : 0u;
            if (b > nkey) { nkey = b; npp = (unsigned)p; }
        }
        // warp argmax (short chain) + independent rank/alive reduces (overlap)
        const unsigned wmax = __reduce_max_sync(FULLMASK, nkey);
        const unsigned ball = __ballot_sync(FULLMASK, nkey == wmax);
        const int wl = __ffs(ball) - 1;
        const unsigned wpp = __shfl_sync(FULLMASK, npp, wl);
        const int wrank  = __reduce_add_sync(FULLMASK, rloc);
        const int walive = __reduce_add_sync(FULLMASK, kloc);
        if (lane == 0)
            bPost[cur ^ 1][warp] = make_uint4(wmax, wpp, (unsigned)wrank, (unsigned)walive);
        __syncthreads();
        cur ^= 1;
    }

    if (t == 0) d_kc[l] = kc;
}

// ---------------- gather + pack outputs ----------------
// Layout (float32): boxes[N*4] | scores[N] | labels[N] | count[1]
__global__ void gather_kernel(const float4* __restrict__ boxes,
                              const float* __restrict__ scores,
                              const int* __restrict__ labels,
                              float* __restrict__ out)
{
    const int j = blockIdx.x * blockDim.x + threadIdx.x;

    int off[LCLS + 1];
    off[0] = 0;
#pragma unroll
    for (int l = 0; l < LCLS; l++) off[l + 1] = off[l] + d_kc[l];
    const int total = off[LCLS];

    if (j == 0) out[NBOX * 6] = (float)total;
    if (j >= NBOX) return;

    float4 b = make_float4(0.f, 0.f, 0.f, 0.f);
    float s = 0.f, lab = 0.f;
    if (j < total) {
        int l = 0;
#pragma unroll
        for (int q = 1; q < LCLS; q++) if (j >= off[q]) l = q;
        const int g = d_keep[l * CAP + (j - off[l])];
        b = boxes[g];
        s = scores[g];
        lab = (float)labels[g];
    }
    reinterpret_cast<float4*>(out)[j] = b;
    out[NBOX * 4 + j] = s;
    out[NBOX * 5 + j] = lab;
}

extern "C" void kernel_launch(void* const* d_in, const int* in_sizes, int n_in,
                              void* d_out, int out_size)
{
    const float4* boxes  = (const float4*)d_in[0];
    const float*  scores = (const float*)d_in[1];
    const int*    labels = (const int*)d_in[2];
    float* out = (float*)d_out;

    softnms_kernel<<<LCLS, NT>>>(boxes, scores, labels);
    gather_kernel<<<NBOX / NT, NT>>>(boxes, scores, labels, out);
}